// round 2
// baseline (speedup 1.0000x reference)
#include <cuda_runtime.h>
#include <math.h>

// ---------------- problem constants ----------------
#define NMAX 50000
// layer1: in 128 -> 4 heads x 32 = 128 ; layer2: 128 -> 1 head x 64

// ---------------- device scratch (no allocs allowed) ----------------
__device__ float    g_xw1 [NMAX * 128];
__device__ float    g_as1 [NMAX * 4];
__device__ float    g_ad1 [NMAX * 4];
__device__ unsigned g_m1  [NMAX * 4];
__device__ float    g_den1[NMAX * 4];
__device__ float    g_out1[NMAX * 128];
__device__ float    g_xw2 [NMAX * 64];
__device__ float    g_as2 [NMAX];
__device__ float    g_ad2 [NMAX];
__device__ unsigned g_m2  [NMAX];
__device__ float    g_den2[NMAX];
__device__ float    g_out2[NMAX * 64];

// ---------------- helpers ----------------
// order-preserving float -> uint encoding for atomicMax on floats
__device__ __forceinline__ unsigned fenc(float f) {
    unsigned b = __float_as_uint(f);
    return (b & 0x80000000u) ? ~b : (b | 0x80000000u);
}
__device__ __forceinline__ float fdec(unsigned u) {
    unsigned b = (u & 0x80000000u) ? (u & 0x7fffffffu) : ~u;
    return __uint_as_float(b);
}
__device__ __forceinline__ float lrelu(float z) { return z > 0.f ? z : 0.2f * z; }

// ---------------- kernels ----------------
__global__ void k_init(float* __restrict__ dout, int n) {
    int i = blockIdx.x * blockDim.x + threadIdx.x;
    int stride = gridDim.x * blockDim.x;
    int tot = n * 128;
    for (; i < tot; i += stride) {
        g_out1[i] = 0.f;
        if (i < n * 64) g_out2[i] = 0.f;
        if (i < n * 4)  { g_den1[i] = 0.f; g_m1[i] = 0u; }
        if (i < n)      { g_den2[i] = 0.f; g_m2[i] = 0u; }
        if (i < 64)     dout[i] = 0.f;
    }
}

// xw1 = x @ W1 ; a_src1/a_dst1 per node. warp per node, thread = 4 cols.
__global__ void k_gemm1(const float* __restrict__ x, const float* __restrict__ W,
                        const float* __restrict__ asv, const float* __restrict__ adv, int n) {
    __shared__ float xs[8][128];
    int w = threadIdx.x >> 5, lane = threadIdx.x & 31;
    int node = blockIdx.x * 8 + w;
    if (node >= n) return;
    float4 xv = *(const float4*)(x + (size_t)node * 128 + lane * 4);
    ((float4*)xs[w])[lane] = xv;
    __syncwarp();
    float4 acc = make_float4(0.f, 0.f, 0.f, 0.f);
    const float* wp = W + lane * 4;
#pragma unroll 8
    for (int k = 0; k < 128; k++) {
        float xk = xs[w][k];
        float4 wv = *(const float4*)(wp + k * 128);
        acc.x = fmaf(xk, wv.x, acc.x);
        acc.y = fmaf(xk, wv.y, acc.y);
        acc.z = fmaf(xk, wv.z, acc.z);
        acc.w = fmaf(xk, wv.w, acc.w);
    }
    *(float4*)(g_xw1 + (size_t)node * 128 + lane * 4) = acc;
    int c0 = lane * 4;
    float s = acc.x * asv[c0] + acc.y * asv[c0 + 1] + acc.z * asv[c0 + 2] + acc.w * asv[c0 + 3];
    float d = acc.x * adv[c0] + acc.y * adv[c0 + 1] + acc.z * adv[c0 + 2] + acc.w * adv[c0 + 3];
    // reduce within each 8-lane group (= one head of 32 cols)
#pragma unroll
    for (int off = 4; off; off >>= 1) {
        s += __shfl_xor_sync(0xffffffffu, s, off);
        d += __shfl_xor_sync(0xffffffffu, d, off);
    }
    if ((lane & 7) == 0) {
        g_as1[node * 4 + (lane >> 3)] = s;
        g_ad1[node * 4 + (lane >> 3)] = d;
    }
}

__global__ void k_max1(const int* __restrict__ ei, int E, int Etot) {
    int e = blockIdx.x * blockDim.x + threadIdx.x;
    if (e >= Etot) return;
    int s, d;
    if (e < E) { s = ei[e]; d = ei[E + e]; } else { s = d = e - E; }
#pragma unroll
    for (int h = 0; h < 4; h++) {
        float z = lrelu(g_as1[s * 4 + h] + g_ad1[d * 4 + h]);
        atomicMax(&g_m1[d * 4 + h], fenc(z));
    }
}

__global__ void k_sum1(const int* __restrict__ ei, int E, int Etot) {
    int e = blockIdx.x * blockDim.x + threadIdx.x;
    if (e >= Etot) return;
    int s, d;
    if (e < E) { s = ei[e]; d = ei[E + e]; } else { s = d = e - E; }
#pragma unroll
    for (int h = 0; h < 4; h++) {
        float z = lrelu(g_as1[s * 4 + h] + g_ad1[d * 4 + h]);
        float ex = __expf(z - fdec(g_m1[d * 4 + h]));
        atomicAdd(&g_den1[d * 4 + h], ex);
    }
}

// warp per edge: out1[dst] += alpha * xw1[src], 128 floats via red.v4
__global__ void k_agg1(const int* __restrict__ ei, int E, int Etot) {
    int gt = blockIdx.x * blockDim.x + threadIdx.x;
    int we = gt >> 5, lane = gt & 31;
    if (we >= Etot) return;
    int s, d;
    if (we < E) { s = ei[we]; d = ei[E + we]; } else { s = d = we - E; }
    int h = lane >> 3;
    float z = lrelu(g_as1[s * 4 + h] + g_ad1[d * 4 + h]);
    float alpha = __expf(z - fdec(g_m1[d * 4 + h])) / (g_den1[d * 4 + h] + 1e-16f);
    float4 v = *(const float4*)(g_xw1 + (size_t)s * 128 + lane * 4);
    float* dst = g_out1 + (size_t)d * 128 + lane * 4;
    asm volatile("red.global.add.v4.f32 [%0], {%1,%2,%3,%4};"
                 :: "l"(dst), "f"(alpha * v.x), "f"(alpha * v.y),
                    "f"(alpha * v.z), "f"(alpha * v.w)
                 : "memory");
}

// h = elu(out1 + b1); xw2 = h @ W2; a_src2/a_dst2. warp per node, thread = 2 cols.
__global__ void k_gemm2(const float* __restrict__ b1, const float* __restrict__ W,
                        const float* __restrict__ asv, const float* __restrict__ adv, int n) {
    __shared__ float hs[8][128];
    int w = threadIdx.x >> 5, lane = threadIdx.x & 31;
    int node = blockIdx.x * 8 + w;
    if (node >= n) return;
    float4 hv = *(const float4*)(g_out1 + (size_t)node * 128 + lane * 4);
    int c0 = lane * 4;
    hv.x += b1[c0];     hv.x = hv.x > 0.f ? hv.x : expm1f(hv.x);
    hv.y += b1[c0 + 1]; hv.y = hv.y > 0.f ? hv.y : expm1f(hv.y);
    hv.z += b1[c0 + 2]; hv.z = hv.z > 0.f ? hv.z : expm1f(hv.z);
    hv.w += b1[c0 + 3]; hv.w = hv.w > 0.f ? hv.w : expm1f(hv.w);
    ((float4*)hs[w])[lane] = hv;
    __syncwarp();
    float2 acc = make_float2(0.f, 0.f);
    const float* wp = W + lane * 2;
#pragma unroll 8
    for (int k = 0; k < 128; k++) {
        float hk = hs[w][k];
        float2 wv = *(const float2*)(wp + k * 64);
        acc.x = fmaf(hk, wv.x, acc.x);
        acc.y = fmaf(hk, wv.y, acc.y);
    }
    *(float2*)(g_xw2 + (size_t)node * 64 + lane * 2) = acc;
    float s = acc.x * asv[lane * 2] + acc.y * asv[lane * 2 + 1];
    float d = acc.x * adv[lane * 2] + acc.y * adv[lane * 2 + 1];
#pragma unroll
    for (int off = 16; off; off >>= 1) {
        s += __shfl_xor_sync(0xffffffffu, s, off);
        d += __shfl_xor_sync(0xffffffffu, d, off);
    }
    if (lane == 0) { g_as2[node] = s; g_ad2[node] = d; }
}

__global__ void k_max2(const int* __restrict__ ei, int E, int Etot) {
    int e = blockIdx.x * blockDim.x + threadIdx.x;
    if (e >= Etot) return;
    int s, d;
    if (e < E) { s = ei[e]; d = ei[E + e]; } else { s = d = e - E; }
    float z = lrelu(g_as2[s] + g_ad2[d]);
    atomicMax(&g_m2[d], fenc(z));
}

__global__ void k_sum2(const int* __restrict__ ei, int E, int Etot) {
    int e = blockIdx.x * blockDim.x + threadIdx.x;
    if (e >= Etot) return;
    int s, d;
    if (e < E) { s = ei[e]; d = ei[E + e]; } else { s = d = e - E; }
    float z = lrelu(g_as2[s] + g_ad2[d]);
    atomicAdd(&g_den2[d], __expf(z - fdec(g_m2[d])));
}

// warp per edge: out2[dst] += alpha * xw2[src], 64 floats via red.v2
__global__ void k_agg2(const int* __restrict__ ei, int E, int Etot) {
    int gt = blockIdx.x * blockDim.x + threadIdx.x;
    int we = gt >> 5, lane = gt & 31;
    if (we >= Etot) return;
    int s, d;
    if (we < E) { s = ei[we]; d = ei[E + we]; } else { s = d = we - E; }
    float z = lrelu(g_as2[s] + g_ad2[d]);
    float alpha = __expf(z - fdec(g_m2[d])) / (g_den2[d] + 1e-16f);
    float2 v = *(const float2*)(g_xw2 + (size_t)s * 64 + lane * 2);
    float* dst = g_out2 + (size_t)d * 64 + lane * 2;
    asm volatile("red.global.add.v2.f32 [%0], {%1,%2};"
                 :: "l"(dst), "f"(alpha * v.x), "f"(alpha * v.y)
                 : "memory");
}

// final: mean over nodes of (out2 + b2) -> 64 floats
__global__ void k_final(const float* __restrict__ b2, float* __restrict__ dout, int n) {
    __shared__ float sm[256];
    int tid = threadIdx.x;
    float local = 0.f;
    float inv = 1.0f / (float)n;
    int total = n * 64;
    for (int i = blockIdx.x * 256 + tid; i < total; i += gridDim.x * 256) {
        int c = i & 63;
        local += (g_out2[i] + b2[c]) * inv;
    }
    sm[tid] = local;
    __syncthreads();
    if (tid < 64) {
        float s2 = sm[tid] + sm[tid + 64] + sm[tid + 128] + sm[tid + 192];
        atomicAdd(&dout[tid], s2);
    }
}

// ---------------- launch ----------------
extern "C" void kernel_launch(void* const* d_in, const int* in_sizes, int n_in,
                              void* d_out, int out_size) {
    const float* x   = (const float*)d_in[0];
    const int*   ei  = (const int*)d_in[1];
    const float* W1  = (const float*)d_in[2];
    const float* as1 = (const float*)d_in[3];
    const float* ad1 = (const float*)d_in[4];
    const float* b1  = (const float*)d_in[5];
    const float* W2  = (const float*)d_in[6];
    const float* as2 = (const float*)d_in[7];
    const float* ad2 = (const float*)d_in[8];
    const float* b2  = (const float*)d_in[9];
    float* out = (float*)d_out;

    int n = in_sizes[0] / 128;
    int E = in_sizes[1] / 2;
    int Etot = E + n;

    k_init <<<512, 256>>>(out, n);
    k_gemm1<<<(n + 7) / 8, 256>>>(x, W1, as1, ad1, n);
    k_max1 <<<(Etot + 255) / 256, 256>>>(ei, E, Etot);
    k_sum1 <<<(Etot + 255) / 256, 256>>>(ei, E, Etot);
    k_agg1 <<<(Etot + 7) / 8, 256>>>(ei, E, Etot);
    k_gemm2<<<(n + 7) / 8, 256>>>(b1, W2, as2, ad2, n);
    k_max2 <<<(Etot + 255) / 256, 256>>>(ei, E, Etot);
    k_sum2 <<<(Etot + 255) / 256, 256>>>(ei, E, Etot);
    k_agg2 <<<(Etot + 7) / 8, 256>>>(ei, E, Etot);
    k_final<<<256, 256>>>(b2, out, n);
}

// round 3
// speedup vs baseline: 1.3822x; 1.3822x over previous
#include <cuda_runtime.h>
#include <math.h>

// ---------------- problem constants ----------------
#define NMAX 50000
// layer1: in 128 -> 4 heads x 32 = 128 ; layer2: 128 -> 1 head x 64

// ---------------- device scratch (no allocs allowed) ----------------
__device__ float g_xw1 [NMAX * 128];
__device__ float g_as1 [NMAX * 4];
__device__ float g_ad1 [NMAX * 4];
__device__ float g_den1[NMAX * 4];
__device__ float g_out1[NMAX * 128];   // unnormalized sum of exp(z)*xw1[src]
__device__ float g_xw2 [NMAX * 64];
__device__ float g_as2 [NMAX];
__device__ float g_ad2 [NMAX];
__device__ float g_den2[NMAX];
__device__ float g_out2[NMAX * 64];    // unnormalized sum of exp(z)*xw2[src]

__device__ __forceinline__ float lrelu(float z) { return z > 0.f ? z : 0.2f * z; }

// ---------------- kernels ----------------
// zero scratch; seed dout with b2 (so final atomics add normalized means on top)
__global__ void k_init(const float* __restrict__ b2, float* __restrict__ dout, int n) {
    int i = blockIdx.x * blockDim.x + threadIdx.x;
    int stride = gridDim.x * blockDim.x;
    int tot = n * 128;
    for (; i < tot; i += stride) {
        g_out1[i] = 0.f;
        if (i < n * 64) g_out2[i] = 0.f;
        if (i < n * 4)  g_den1[i] = 0.f;
        if (i < n)      g_den2[i] = 0.f;
        if (i < 64)     dout[i] = b2[i];
    }
}

// xw1 = x @ W1 ; a_src1/a_dst1. 4 nodes per warp -> 4x W reuse per load.
__global__ void k_gemm1(const float* __restrict__ x, const float* __restrict__ W,
                        const float* __restrict__ asv, const float* __restrict__ adv, int n) {
    __shared__ float xs[32][128];
    int w = threadIdx.x >> 5, lane = threadIdx.x & 31;
    int node0 = blockIdx.x * 32 + w * 4;
    int c0 = lane * 4;
#pragma unroll
    for (int i = 0; i < 4; i++) {
        int nd = node0 + i;
        if (nd < n)
            ((float4*)xs[w * 4 + i])[lane] = *(const float4*)(x + (size_t)nd * 128 + c0);
    }
    __syncwarp();
    float4 acc0 = make_float4(0,0,0,0), acc1 = acc0, acc2 = acc0, acc3 = acc0;
    const float* wp = W + c0;
#pragma unroll 4
    for (int k = 0; k < 128; k++) {
        float4 wv = *(const float4*)(wp + k * 128);
        float x0 = xs[w*4+0][k], x1 = xs[w*4+1][k], x2 = xs[w*4+2][k], x3 = xs[w*4+3][k];
        acc0.x = fmaf(x0, wv.x, acc0.x); acc0.y = fmaf(x0, wv.y, acc0.y);
        acc0.z = fmaf(x0, wv.z, acc0.z); acc0.w = fmaf(x0, wv.w, acc0.w);
        acc1.x = fmaf(x1, wv.x, acc1.x); acc1.y = fmaf(x1, wv.y, acc1.y);
        acc1.z = fmaf(x1, wv.z, acc1.z); acc1.w = fmaf(x1, wv.w, acc1.w);
        acc2.x = fmaf(x2, wv.x, acc2.x); acc2.y = fmaf(x2, wv.y, acc2.y);
        acc2.z = fmaf(x2, wv.z, acc2.z); acc2.w = fmaf(x2, wv.w, acc2.w);
        acc3.x = fmaf(x3, wv.x, acc3.x); acc3.y = fmaf(x3, wv.y, acc3.y);
        acc3.z = fmaf(x3, wv.z, acc3.z); acc3.w = fmaf(x3, wv.w, acc3.w);
    }
    float4 av = *(const float4*)(asv + c0);
    float4 dv = *(const float4*)(adv + c0);
    float4 accs[4] = {acc0, acc1, acc2, acc3};
#pragma unroll
    for (int i = 0; i < 4; i++) {
        int nd = node0 + i;
        if (nd >= n) continue;
        float4 a = accs[i];
        *(float4*)(g_xw1 + (size_t)nd * 128 + c0) = a;
        float s = a.x * av.x + a.y * av.y + a.z * av.z + a.w * av.w;
        float d = a.x * dv.x + a.y * dv.y + a.z * dv.z + a.w * dv.w;
#pragma unroll
        for (int off = 4; off; off >>= 1) {
            s += __shfl_xor_sync(0xffffffffu, s, off);
            d += __shfl_xor_sync(0xffffffffu, d, off);
        }
        if ((lane & 7) == 0) {
            g_as1[nd * 4 + (lane >> 3)] = s;
            g_ad1[nd * 4 + (lane >> 3)] = d;
        }
    }
}

// single fused edge pass: out1[dst] += exp(z)*xw1[src], den1[dst] += exp(z)
__global__ void k_agg1(const int* __restrict__ ei, int E, int Etot) {
    int gt = blockIdx.x * blockDim.x + threadIdx.x;
    int we = gt >> 5, lane = gt & 31;
    if (we >= Etot) return;
    int s, d;
    if (we < E) { s = ei[we]; d = ei[E + we]; } else { s = d = we - E; }
    int h = lane >> 3;
    float ew = __expf(lrelu(g_as1[s * 4 + h] + g_ad1[d * 4 + h]));
    if ((lane & 7) == 0) atomicAdd(&g_den1[d * 4 + h], ew);
    float4 v = *(const float4*)(g_xw1 + (size_t)s * 128 + lane * 4);
    float* dst = g_out1 + (size_t)d * 128 + lane * 4;
    asm volatile("red.global.add.v4.f32 [%0], {%1,%2,%3,%4};"
                 :: "l"(dst), "f"(ew * v.x), "f"(ew * v.y),
                    "f"(ew * v.z), "f"(ew * v.w)
                 : "memory");
}

// h = elu(out1/den1 + b1); xw2 = h @ W2; a_src2/a_dst2. 4 nodes per warp.
__global__ void k_gemm2(const float* __restrict__ b1, const float* __restrict__ W,
                        const float* __restrict__ asv, const float* __restrict__ adv, int n) {
    __shared__ float hs[32][128];
    int w = threadIdx.x >> 5, lane = threadIdx.x & 31;
    int node0 = blockIdx.x * 32 + w * 4;
    int c0 = lane * 4;
    float4 bv = *(const float4*)(b1 + c0);
#pragma unroll
    for (int i = 0; i < 4; i++) {
        int nd = node0 + i;
        if (nd >= n) continue;
        float4 hv = *(const float4*)(g_out1 + (size_t)nd * 128 + c0);
        float inv = 1.0f / (g_den1[nd * 4 + (lane >> 3)] + 1e-16f);
        hv.x = hv.x * inv + bv.x; hv.x = hv.x > 0.f ? hv.x : expm1f(hv.x);
        hv.y = hv.y * inv + bv.y; hv.y = hv.y > 0.f ? hv.y : expm1f(hv.y);
        hv.z = hv.z * inv + bv.z; hv.z = hv.z > 0.f ? hv.z : expm1f(hv.z);
        hv.w = hv.w * inv + bv.w; hv.w = hv.w > 0.f ? hv.w : expm1f(hv.w);
        ((float4*)hs[w * 4 + i])[lane] = hv;
    }
    __syncwarp();
    float2 acc0 = make_float2(0,0), acc1 = acc0, acc2 = acc0, acc3 = acc0;
    const float* wp = W + lane * 2;
#pragma unroll 4
    for (int k = 0; k < 128; k++) {
        float2 wv = *(const float2*)(wp + k * 64);
        float x0 = hs[w*4+0][k], x1 = hs[w*4+1][k], x2 = hs[w*4+2][k], x3 = hs[w*4+3][k];
        acc0.x = fmaf(x0, wv.x, acc0.x); acc0.y = fmaf(x0, wv.y, acc0.y);
        acc1.x = fmaf(x1, wv.x, acc1.x); acc1.y = fmaf(x1, wv.y, acc1.y);
        acc2.x = fmaf(x2, wv.x, acc2.x); acc2.y = fmaf(x2, wv.y, acc2.y);
        acc3.x = fmaf(x3, wv.x, acc3.x); acc3.y = fmaf(x3, wv.y, acc3.y);
    }
    float2 av = *(const float2*)(asv + lane * 2);
    float2 dv = *(const float2*)(adv + lane * 2);
    float2 accs[4] = {acc0, acc1, acc2, acc3};
#pragma unroll
    for (int i = 0; i < 4; i++) {
        int nd = node0 + i;
        if (nd >= n) continue;
        float2 a = accs[i];
        *(float2*)(g_xw2 + (size_t)nd * 64 + lane * 2) = a;
        float s = a.x * av.x + a.y * av.y;
        float d = a.x * dv.x + a.y * dv.y;
#pragma unroll
        for (int off = 16; off; off >>= 1) {
            s += __shfl_xor_sync(0xffffffffu, s, off);
            d += __shfl_xor_sync(0xffffffffu, d, off);
        }
        if (lane == 0) { g_as2[nd] = s; g_ad2[nd] = d; }
    }
}

// fused edge pass 2: out2[dst] += exp(z)*xw2[src], den2[dst] += exp(z)
__global__ void k_agg2(const int* __restrict__ ei, int E, int Etot) {
    int gt = blockIdx.x * blockDim.x + threadIdx.x;
    int we = gt >> 5, lane = gt & 31;
    if (we >= Etot) return;
    int s, d;
    if (we < E) { s = ei[we]; d = ei[E + we]; } else { s = d = we - E; }
    float ew = __expf(lrelu(g_as2[s] + g_ad2[d]));
    if (lane == 0) atomicAdd(&g_den2[d], ew);
    float2 v = *(const float2*)(g_xw2 + (size_t)s * 64 + lane * 2);
    float* dst = g_out2 + (size_t)d * 64 + lane * 2;
    asm volatile("red.global.add.v2.f32 [%0], {%1,%2};"
                 :: "l"(dst), "f"(ew * v.x), "f"(ew * v.y)
                 : "memory");
}

// final: dout[c] = b2[c] (from init) + mean_n( out2[n][c] / den2[n] )
__global__ void k_final(float* __restrict__ dout, int n) {
    __shared__ float sm[256];
    int tid = threadIdx.x;
    float local = 0.f;
    float inv = 1.0f / (float)n;
    int total = n * 64;
    for (int i = blockIdx.x * 256 + tid; i < total; i += gridDim.x * 256) {
        int node = i >> 6;
        local += g_out2[i] / (g_den2[node] + 1e-16f) * inv;
    }
    sm[tid] = local;
    __syncthreads();
    if (tid < 64) {
        float s2 = sm[tid] + sm[tid + 64] + sm[tid + 128] + sm[tid + 192];
        atomicAdd(&dout[tid], s2);
    }
}

// ---------------- launch ----------------
extern "C" void kernel_launch(void* const* d_in, const int* in_sizes, int n_in,
                              void* d_out, int out_size) {
    const float* x   = (const float*)d_in[0];
    const int*   ei  = (const int*)d_in[1];
    const float* W1  = (const float*)d_in[2];
    const float* as1 = (const float*)d_in[3];
    const float* ad1 = (const float*)d_in[4];
    const float* b1  = (const float*)d_in[5];
    const float* W2  = (const float*)d_in[6];
    const float* as2 = (const float*)d_in[7];
    const float* ad2 = (const float*)d_in[8];
    const float* b2  = (const float*)d_in[9];
    float* out = (float*)d_out;

    int n = in_sizes[0] / 128;
    int E = in_sizes[1] / 2;
    int Etot = E + n;

    k_init <<<512, 256>>>(b2, out, n);
    k_gemm1<<<(n + 31) / 32, 256>>>(x, W1, as1, ad1, n);
    k_agg1 <<<(Etot + 7) / 8, 256>>>(ei, E, Etot);
    k_gemm2<<<(n + 31) / 32, 256>>>(b1, W2, as2, ad2, n);
    k_agg2 <<<(Etot + 7) / 8, 256>>>(ei, E, Etot);
    k_final<<<256, 256>>>(out, n);
}

// round 4
// speedup vs baseline: 2.2387x; 1.6196x over previous
#include <cuda_runtime.h>
#include <math.h>

// ---------------- problem constants ----------------
#define NMAX 50000
#define EMAX 1700000   // 1.6M edges + 50k self-loops

// ---------------- device scratch (no allocs allowed) ----------------
__device__ float g_xw1 [NMAX * 128];
__device__ float g_as1 [NMAX * 4];
__device__ float g_ad1 [NMAX * 4];
__device__ float g_h   [NMAX * 128];   // elu(normalized agg1 + b1)
__device__ float g_xw2 [NMAX * 64];
__device__ float g_as2 [NMAX];
__device__ float g_ad2 [NMAX];
__device__ float g_out2[NMAX * 64];    // normalized layer-2 output (pre-bias)

// CSR by destination (built once per call, shared by both layers)
__device__ int g_cnt   [NMAX];
__device__ int g_rowst [NMAX + 1];
__device__ int g_cursor[NMAX];
__device__ int g_csrc  [EMAX];

__device__ __forceinline__ float lrelu(float z) { return z > 0.f ? z : 0.2f * z; }

// ---------------- CSR build ----------------
__global__ void k_init(const float* __restrict__ b2, float* __restrict__ dout, int n) {
    int i = blockIdx.x * blockDim.x + threadIdx.x;
    if (i < n)  g_cnt[i] = 0;
    if (i < 64) dout[i] = b2[i];
}

__global__ void k_hist(const int* __restrict__ ei, int E, int Etot) {
    int e = blockIdx.x * blockDim.x + threadIdx.x;
    if (e >= Etot) return;
    int d = (e < E) ? ei[E + e] : (e - E);
    atomicAdd(&g_cnt[d], 1);
}

// single-block exclusive scan over n counts -> rowst[0..n], cursor = rowst
__global__ void k_scan(int n) {
    __shared__ int sm[1024];
    int t = threadIdx.x;
    int chunk = (n + 1023) / 1024;
    int beg = t * chunk, end = min(beg + chunk, n);
    int tot = 0;
    for (int i = beg; i < end; i++) tot += g_cnt[i];
    sm[t] = tot;
    __syncthreads();
    // Hillis-Steele inclusive scan
    for (int off = 1; off < 1024; off <<= 1) {
        int v = (t >= off) ? sm[t - off] : 0;
        __syncthreads();
        sm[t] += v;
        __syncthreads();
    }
    int base = sm[t] - tot;   // exclusive prefix for this chunk
    for (int i = beg; i < end; i++) {
        g_rowst[i] = base;
        g_cursor[i] = base;
        base += g_cnt[i];
    }
    if (t == 0) g_rowst[n] = sm[1023];
}

__global__ void k_scatter(const int* __restrict__ ei, int E, int Etot) {
    int e = blockIdx.x * blockDim.x + threadIdx.x;
    if (e >= Etot) return;
    int s, d;
    if (e < E) { s = ei[e]; d = ei[E + e]; } else { s = d = e - E; }
    int pos = atomicAdd(&g_cursor[d], 1);
    g_csrc[pos] = s;
}

// ---------------- layer kernels ----------------
// xw1 = x @ W1 ; a_src1/a_dst1. 4 nodes per warp -> 4x W reuse per load.
__global__ void k_gemm1(const float* __restrict__ x, const float* __restrict__ W,
                        const float* __restrict__ asv, const float* __restrict__ adv, int n) {
    __shared__ float xs[32][128];
    int w = threadIdx.x >> 5, lane = threadIdx.x & 31;
    int node0 = blockIdx.x * 32 + w * 4;
    int c0 = lane * 4;
#pragma unroll
    for (int i = 0; i < 4; i++) {
        int nd = node0 + i;
        if (nd < n)
            ((float4*)xs[w * 4 + i])[lane] = *(const float4*)(x + (size_t)nd * 128 + c0);
    }
    __syncwarp();
    float4 acc0 = make_float4(0,0,0,0), acc1 = acc0, acc2 = acc0, acc3 = acc0;
    const float* wp = W + c0;
#pragma unroll 4
    for (int k = 0; k < 128; k++) {
        float4 wv = *(const float4*)(wp + k * 128);
        float x0 = xs[w*4+0][k], x1 = xs[w*4+1][k], x2 = xs[w*4+2][k], x3 = xs[w*4+3][k];
        acc0.x = fmaf(x0, wv.x, acc0.x); acc0.y = fmaf(x0, wv.y, acc0.y);
        acc0.z = fmaf(x0, wv.z, acc0.z); acc0.w = fmaf(x0, wv.w, acc0.w);
        acc1.x = fmaf(x1, wv.x, acc1.x); acc1.y = fmaf(x1, wv.y, acc1.y);
        acc1.z = fmaf(x1, wv.z, acc1.z); acc1.w = fmaf(x1, wv.w, acc1.w);
        acc2.x = fmaf(x2, wv.x, acc2.x); acc2.y = fmaf(x2, wv.y, acc2.y);
        acc2.z = fmaf(x2, wv.z, acc2.z); acc2.w = fmaf(x2, wv.w, acc2.w);
        acc3.x = fmaf(x3, wv.x, acc3.x); acc3.y = fmaf(x3, wv.y, acc3.y);
        acc3.w = fmaf(x3, wv.w, acc3.w); acc3.z = fmaf(x3, wv.z, acc3.z);
    }
    float4 av = *(const float4*)(asv + c0);
    float4 dv = *(const float4*)(adv + c0);
    float4 accs[4] = {acc0, acc1, acc2, acc3};
#pragma unroll
    for (int i = 0; i < 4; i++) {
        int nd = node0 + i;
        if (nd >= n) continue;
        float4 a = accs[i];
        *(float4*)(g_xw1 + (size_t)nd * 128 + c0) = a;
        float s = a.x * av.x + a.y * av.y + a.z * av.z + a.w * av.w;
        float d = a.x * dv.x + a.y * dv.y + a.z * dv.z + a.w * dv.w;
#pragma unroll
        for (int off = 4; off; off >>= 1) {
            s += __shfl_xor_sync(0xffffffffu, s, off);
            d += __shfl_xor_sync(0xffffffffu, d, off);
        }
        if ((lane & 7) == 0) {
            g_as1[nd * 4 + (lane >> 3)] = s;
            g_ad1[nd * 4 + (lane >> 3)] = d;
        }
    }
}

// gather agg layer1: warp per dst node. acc = sum exp(z)*xw1[src]; den = sum exp(z).
// epilogue writes h = elu(acc/den + b1).
__global__ void k_agg1(const float* __restrict__ b1, int n) {
    int gt = blockIdx.x * blockDim.x + threadIdx.x;
    int nd = gt >> 5, lane = gt & 31;
    if (nd >= n) return;
    int h = lane >> 3, c0 = lane * 4;
    int beg = g_rowst[nd], end = g_rowst[nd + 1];
    float adh = g_ad1[nd * 4 + h];
    float4 acc = make_float4(0,0,0,0);
    float den = 0.f;
    int j = beg;
    for (; j + 1 < end; j += 2) {
        int s0 = g_csrc[j], s1 = g_csrc[j + 1];
        float ew0 = __expf(lrelu(g_as1[s0 * 4 + h] + adh));
        float ew1 = __expf(lrelu(g_as1[s1 * 4 + h] + adh));
        float4 v0 = *(const float4*)(g_xw1 + (size_t)s0 * 128 + c0);
        float4 v1 = *(const float4*)(g_xw1 + (size_t)s1 * 128 + c0);
        acc.x = fmaf(ew0, v0.x, acc.x); acc.y = fmaf(ew0, v0.y, acc.y);
        acc.z = fmaf(ew0, v0.z, acc.z); acc.w = fmaf(ew0, v0.w, acc.w);
        acc.x = fmaf(ew1, v1.x, acc.x); acc.y = fmaf(ew1, v1.y, acc.y);
        acc.z = fmaf(ew1, v1.z, acc.z); acc.w = fmaf(ew1, v1.w, acc.w);
        den += ew0 + ew1;
    }
    if (j < end) {
        int s0 = g_csrc[j];
        float ew0 = __expf(lrelu(g_as1[s0 * 4 + h] + adh));
        float4 v0 = *(const float4*)(g_xw1 + (size_t)s0 * 128 + c0);
        acc.x = fmaf(ew0, v0.x, acc.x); acc.y = fmaf(ew0, v0.y, acc.y);
        acc.z = fmaf(ew0, v0.z, acc.z); acc.w = fmaf(ew0, v0.w, acc.w);
        den += ew0;
    }
    float inv = 1.0f / (den + 1e-16f);
    float4 bv = *(const float4*)(b1 + c0);
    float4 hv;
    hv.x = acc.x * inv + bv.x; hv.x = hv.x > 0.f ? hv.x : expm1f(hv.x);
    hv.y = acc.y * inv + bv.y; hv.y = hv.y > 0.f ? hv.y : expm1f(hv.y);
    hv.z = acc.z * inv + bv.z; hv.z = hv.z > 0.f ? hv.z : expm1f(hv.z);
    hv.w = acc.w * inv + bv.w; hv.w = hv.w > 0.f ? hv.w : expm1f(hv.w);
    *(float4*)(g_h + (size_t)nd * 128 + c0) = hv;
}

// xw2 = h @ W2; a_src2/a_dst2. 4 nodes per warp.
__global__ void k_gemm2(const float* __restrict__ W,
                        const float* __restrict__ asv, const float* __restrict__ adv, int n) {
    __shared__ float hs[32][128];
    int w = threadIdx.x >> 5, lane = threadIdx.x & 31;
    int node0 = blockIdx.x * 32 + w * 4;
    int c0 = lane * 4;
#pragma unroll
    for (int i = 0; i < 4; i++) {
        int nd = node0 + i;
        if (nd < n)
            ((float4*)hs[w * 4 + i])[lane] = *(const float4*)(g_h + (size_t)nd * 128 + c0);
    }
    __syncwarp();
    float2 acc0 = make_float2(0,0), acc1 = acc0, acc2 = acc0, acc3 = acc0;
    const float* wp = W + lane * 2;
#pragma unroll 4
    for (int k = 0; k < 128; k++) {
        float2 wv = *(const float2*)(wp + k * 64);
        float x0 = hs[w*4+0][k], x1 = hs[w*4+1][k], x2 = hs[w*4+2][k], x3 = hs[w*4+3][k];
        acc0.x = fmaf(x0, wv.x, acc0.x); acc0.y = fmaf(x0, wv.y, acc0.y);
        acc1.x = fmaf(x1, wv.x, acc1.x); acc1.y = fmaf(x1, wv.y, acc1.y);
        acc2.x = fmaf(x2, wv.x, acc2.x); acc2.y = fmaf(x2, wv.y, acc2.y);
        acc3.x = fmaf(x3, wv.x, acc3.x); acc3.y = fmaf(x3, wv.y, acc3.y);
    }
    float2 av = *(const float2*)(asv + lane * 2);
    float2 dv = *(const float2*)(adv + lane * 2);
    float2 accs[4] = {acc0, acc1, acc2, acc3};
#pragma unroll
    for (int i = 0; i < 4; i++) {
        int nd = node0 + i;
        if (nd >= n) continue;
        float2 a = accs[i];
        *(float2*)(g_xw2 + (size_t)nd * 64 + lane * 2) = a;
        float s = a.x * av.x + a.y * av.y;
        float d = a.x * dv.x + a.y * dv.y;
#pragma unroll
        for (int off = 16; off; off >>= 1) {
            s += __shfl_xor_sync(0xffffffffu, s, off);
            d += __shfl_xor_sync(0xffffffffu, d, off);
        }
        if (lane == 0) { g_as2[nd] = s; g_ad2[nd] = d; }
    }
}

// gather agg layer2: warp per dst node, lane = 2 cols. writes normalized out2.
__global__ void k_agg2(int n) {
    int gt = blockIdx.x * blockDim.x + threadIdx.x;
    int nd = gt >> 5, lane = gt & 31;
    if (nd >= n) return;
    int c0 = lane * 2;
    int beg = g_rowst[nd], end = g_rowst[nd + 1];
    float adh = g_ad2[nd];
    float2 acc = make_float2(0,0);
    float den = 0.f;
    int j = beg;
    for (; j + 1 < end; j += 2) {
        int s0 = g_csrc[j], s1 = g_csrc[j + 1];
        float ew0 = __expf(lrelu(g_as2[s0] + adh));
        float ew1 = __expf(lrelu(g_as2[s1] + adh));
        float2 v0 = *(const float2*)(g_xw2 + (size_t)s0 * 64 + c0);
        float2 v1 = *(const float2*)(g_xw2 + (size_t)s1 * 64 + c0);
        acc.x = fmaf(ew0, v0.x, acc.x); acc.y = fmaf(ew0, v0.y, acc.y);
        acc.x = fmaf(ew1, v1.x, acc.x); acc.y = fmaf(ew1, v1.y, acc.y);
        den += ew0 + ew1;
    }
    if (j < end) {
        int s0 = g_csrc[j];
        float ew0 = __expf(lrelu(g_as2[s0] + adh));
        float2 v0 = *(const float2*)(g_xw2 + (size_t)s0 * 64 + c0);
        acc.x = fmaf(ew0, v0.x, acc.x); acc.y = fmaf(ew0, v0.y, acc.y);
        den += ew0;
    }
    float inv = 1.0f / (den + 1e-16f);
    float2 o = make_float2(acc.x * inv, acc.y * inv);
    *(float2*)(g_out2 + (size_t)nd * 64 + c0) = o;
}

// final: dout[c] = b2[c] (seeded in init) + mean_n out2[n][c]
__global__ void k_final(float* __restrict__ dout, int n) {
    __shared__ float sm[256];
    int tid = threadIdx.x;
    float local = 0.f;
    float inv = 1.0f / (float)n;
    int total = n * 64;
    for (int i = blockIdx.x * 256 + tid; i < total; i += gridDim.x * 256)
        local += g_out2[i] * inv;
    sm[tid] = local;
    __syncthreads();
    if (tid < 64) {
        float s2 = sm[tid] + sm[tid + 64] + sm[tid + 128] + sm[tid + 192];
        atomicAdd(&dout[tid], s2);
    }
}

// ---------------- launch ----------------
extern "C" void kernel_launch(void* const* d_in, const int* in_sizes, int n_in,
                              void* d_out, int out_size) {
    const float* x   = (const float*)d_in[0];
    const int*   ei  = (const int*)d_in[1];
    const float* W1  = (const float*)d_in[2];
    const float* as1 = (const float*)d_in[3];
    const float* ad1 = (const float*)d_in[4];
    const float* b1  = (const float*)d_in[5];
    const float* W2  = (const float*)d_in[6];
    const float* as2 = (const float*)d_in[7];
    const float* ad2 = (const float*)d_in[8];
    const float* b2  = (const float*)d_in[9];
    float* out = (float*)d_out;

    int n = in_sizes[0] / 128;
    int E = in_sizes[1] / 2;
    int Etot = E + n;

    k_init   <<<(n + 255) / 256, 256>>>(b2, out, n);
    k_hist   <<<(Etot + 255) / 256, 256>>>(ei, E, Etot);
    k_scan   <<<1, 1024>>>(n);
    k_scatter<<<(Etot + 255) / 256, 256>>>(ei, E, Etot);
    k_gemm1  <<<(n + 31) / 32, 256>>>(x, W1, as1, ad1, n);
    k_agg1   <<<(n + 7) / 8, 256>>>(b1, n);
    k_gemm2  <<<(n + 31) / 32, 256>>>(W2, as2, ad2, n);
    k_agg2   <<<(n + 7) / 8, 256>>>(n);
    k_final  <<<256, 256>>>(out, n);
}